// round 3
// baseline (speedup 1.0000x reference)
#include <cuda_runtime.h>

// Problem constants
#define Gn    4
#define Mn    4096
#define Dn    128
#define NPG   16384           // queries per group (BS)
#define NTILE 128
#define MTILE 128

#define XQ_SIZE  (NPG * Gn * Dn)          // 8388608 floats: x_quant
#define IND_BASE (XQ_SIZE)                // + 65536 floats: indices (as float)
#define CNT_BASE (XQ_SIZE + NPG * Gn)     // + 16384 floats: new_count

// scratch: per-embedding squared norms (allocation-free device global)
__device__ float g_e2[Gn * Mn];

// ---------------------------------------------------------------------------
// prep: e2[g,m] = sum_k emb[g,m,k]^2  (one warp per row) + copy count -> out
// ---------------------------------------------------------------------------
__global__ void prep_kernel(const float* __restrict__ emb,
                            const float* __restrict__ count,
                            float* __restrict__ out) {
    int gtid = blockIdx.x * blockDim.x + threadIdx.x;
    int row  = gtid >> 5;            // warp id == embedding row (0..16383)
    int lane = threadIdx.x & 31;
    if (row < Gn * Mn) {
        float4 v = ((const float4*)(emb + (size_t)row * Dn))[lane];
        float s = v.x * v.x + v.y * v.y + v.z * v.z + v.w * v.w;
        #pragma unroll
        for (int o = 16; o; o >>= 1) s += __shfl_xor_sync(0xffffffffu, s, o);
        if (lane == 0) g_e2[row] = s;
    }
    if (gtid < Gn * Mn) out[CNT_BASE + gtid] = count[gtid];
}

// ---------------------------------------------------------------------------
// main: per CTA = (group g, 128-row n-tile). Loop m-tiles of 128, fp32 GEMM
// with 8x8 register blocking, argmin epilogue, then gather + histogram.
// ---------------------------------------------------------------------------
__global__ __launch_bounds__(256, 1)
void vq_kernel(const float* __restrict__ x,
               const float* __restrict__ emb,
               float* __restrict__ out) {
    extern __shared__ float smem[];
    float* Xs = smem;                 // [Dn][NTILE]  (k-major, 64 KB)
    float* Es = smem + Dn * NTILE;    // [Dn][MTILE]  (k-major, 64 KB)
    __shared__ int winner[NTILE];

    const int g   = blockIdx.y;
    const int n0  = blockIdx.x * NTILE;
    const int tid = threadIdx.x;
    const int ty  = tid >> 4;         // 0..15  (row group:  rows ty*8..ty*8+7)
    const int tx  = tid & 15;         // 0..15  (col group:  cols tx*8..tx*8+7)

    // ---- load X tile transposed into Xs[k][n] ----
    // x layout: (n, g, d) row-major -> vector (g, n) at ((n*Gn + g) * Dn)
    for (int i = tid; i < NTILE * 32; i += 256) {
        int n  = i & 127;
        int kv = i >> 7;              // 0..31 (float4 index along k)
        float4 v = *(const float4*)(x + ((size_t)(n0 + n) * Gn + g) * Dn + kv * 4);
        Xs[(kv * 4 + 0) * NTILE + n] = v.x;
        Xs[(kv * 4 + 1) * NTILE + n] = v.y;
        Xs[(kv * 4 + 2) * NTILE + n] = v.z;
        Xs[(kv * 4 + 3) * NTILE + n] = v.w;
    }

    float bestv[8];
    int   bestidx[8];
    #pragma unroll
    for (int i = 0; i < 8; i++) { bestv[i] = 3.4e38f; bestidx[i] = 0; }

    for (int m0 = 0; m0 < Mn; m0 += MTILE) {
        __syncthreads();
        // ---- load E tile transposed into Es[k][m] ----
        for (int i = tid; i < MTILE * 32; i += 256) {
            int m  = i & 127;
            int kv = i >> 7;
            float4 v = *(const float4*)(emb + ((size_t)g * Mn + m0 + m) * Dn + kv * 4);
            Es[(kv * 4 + 0) * MTILE + m] = v.x;
            Es[(kv * 4 + 1) * MTILE + m] = v.y;
            Es[(kv * 4 + 2) * MTILE + m] = v.z;
            Es[(kv * 4 + 3) * MTILE + m] = v.w;
        }
        __syncthreads();

        float acc[8][8];
        #pragma unroll
        for (int i = 0; i < 8; i++)
            #pragma unroll
            for (int j = 0; j < 8; j++) acc[i][j] = 0.0f;

        #pragma unroll 4
        for (int k = 0; k < Dn; k++) {
            float a[8], b[8];
            *(float4*)(a)     = *(const float4*)(Xs + k * NTILE + ty * 8);
            *(float4*)(a + 4) = *(const float4*)(Xs + k * NTILE + ty * 8 + 4);
            *(float4*)(b)     = *(const float4*)(Es + k * MTILE + tx * 8);
            *(float4*)(b + 4) = *(const float4*)(Es + k * MTILE + tx * 8 + 4);
            #pragma unroll
            for (int i = 0; i < 8; i++)
                #pragma unroll
                for (int j = 0; j < 8; j++)
                    acc[i][j] = fmaf(a[i], b[j], acc[i][j]);
        }

        // ---- argmin epilogue: score = e2 - 2*dot (x^2 is row-constant) ----
        #pragma unroll
        for (int j = 0; j < 8; j++) {
            int   midx = m0 + tx * 8 + j;
            float e2   = g_e2[g * Mn + midx];
            #pragma unroll
            for (int i = 0; i < 8; i++) {
                float s = fmaf(-2.0f, acc[i][j], e2);
                if (s < bestv[i]) { bestv[i] = s; bestidx[i] = midx; }
            }
        }
    }
    __syncthreads();

    // ---- cross-thread reduction (16 candidates per row), reuse Xs ----
    float* rv = Xs;                           // [128][16]
    int*   ri = (int*)(Xs + NTILE * 16);      // [128][16]
    #pragma unroll
    for (int i = 0; i < 8; i++) {
        rv[(ty * 8 + i) * 16 + tx] = bestv[i];
        ri[(ty * 8 + i) * 16 + tx] = bestidx[i];
    }
    __syncthreads();

    if (tid < NTILE) {
        int row = tid;
        float bv = rv[row * 16];
        int   bi = ri[row * 16];
        #pragma unroll
        for (int t = 1; t < 16; t++) {
            float v  = rv[row * 16 + t];
            int   id = ri[row * 16 + t];
            if (v < bv || (v == bv && id < bi)) { bv = v; bi = id; }
        }
        winner[row] = bi;
        int nglob = n0 + row;
        out[IND_BASE + (size_t)nglob * Gn + g] = (float)bi;          // index
        atomicAdd(&out[CNT_BASE + g * Mn + bi], 1.0f);               // histogram
    }
    __syncthreads();

    // ---- gather x_quant: copy winning embedding rows (coalesced) ----
    for (int i = tid; i < NTILE * 32; i += 256) {
        int row = i >> 5;
        int c4  = i & 31;
        int bi  = winner[row];
        float4 v = *(const float4*)(emb + ((size_t)g * Mn + bi) * Dn + c4 * 4);
        *(float4*)(out + ((size_t)(n0 + row) * Gn + g) * Dn + c4 * 4) = v;
    }
}

// ---------------------------------------------------------------------------
extern "C" void kernel_launch(void* const* d_in, const int* in_sizes, int n_in,
                              void* d_out, int out_size) {
    const float* x     = (const float*)d_in[0];
    const float* emb   = (const float*)d_in[1];
    const float* count = (const float*)d_in[2];
    float*       out   = (float*)d_out;

    const int smem_bytes = 2 * Dn * NTILE * (int)sizeof(float);   // 128 KB
    cudaFuncSetAttribute(vq_kernel,
                         cudaFuncAttributeMaxDynamicSharedMemorySize, smem_bytes);

    // prep: 16384 warps (one per embedding row) + count copy
    prep_kernel<<<(Gn * Mn * 32 + 255) / 256, 256>>>(emb, count, out);

    dim3 grid(NPG / NTILE, Gn);
    vq_kernel<<<grid, 256, smem_bytes>>>(x, emb, out);
}

// round 4
// speedup vs baseline: 1.0020x; 1.0020x over previous
#include <cuda_runtime.h>

// Problem constants
#define Gn    4
#define Mn    4096
#define Dn    128
#define NPG   16384           // queries per group (BS)
#define NTILE 128
#define MTILE 128

#define XQ_SIZE  (NPG * Gn * Dn)          // 8388608 floats: x_quant
#define IND_BASE (XQ_SIZE)                // + 65536 floats: indices (as float)
#define CNT_BASE (XQ_SIZE + NPG * Gn)     // + 16384 floats: new_count

// scratch: per-embedding squared norms (allocation-free device global)
__device__ float g_e2[Gn * Mn];

// ---------------------------------------------------------------------------
// prep: e2[g,m] = sum_k emb[g,m,k]^2  (one warp per row) + copy count -> out
// ---------------------------------------------------------------------------
__global__ void prep_kernel(const float* __restrict__ emb,
                            const float* __restrict__ count,
                            float* __restrict__ out) {
    int gtid = blockIdx.x * blockDim.x + threadIdx.x;
    int row  = gtid >> 5;            // warp id == embedding row (0..16383)
    int lane = threadIdx.x & 31;
    if (row < Gn * Mn) {
        float4 v = ((const float4*)(emb + (size_t)row * Dn))[lane];
        float s = v.x * v.x + v.y * v.y + v.z * v.z + v.w * v.w;
        #pragma unroll
        for (int o = 16; o; o >>= 1) s += __shfl_xor_sync(0xffffffffu, s, o);
        if (lane == 0) g_e2[row] = s;
    }
    if (gtid < Gn * Mn) out[CNT_BASE + gtid] = count[gtid];
}

// ---------------------------------------------------------------------------
// main: per CTA = (group g, 128-row n-tile). Loop m-tiles of 128, fp32 GEMM
// with 8x8 register blocking, argmin epilogue, then gather + histogram.
// ---------------------------------------------------------------------------
__global__ __launch_bounds__(256, 1)
void vq_kernel(const float* __restrict__ x,
               const float* __restrict__ emb,
               float* __restrict__ out) {
    extern __shared__ float smem[];
    float* Xs = smem;                 // [Dn][NTILE]  (k-major, 64 KB)
    float* Es = smem + Dn * NTILE;    // [Dn][MTILE]  (k-major, 64 KB)
    __shared__ int winner[NTILE];

    const int g   = blockIdx.y;
    const int n0  = blockIdx.x * NTILE;
    const int tid = threadIdx.x;
    const int ty  = tid >> 4;         // 0..15  (row group:  rows ty*8..ty*8+7)
    const int tx  = tid & 15;         // 0..15  (col group:  cols tx*8..tx*8+7)

    // ---- load X tile transposed into Xs[k][n] ----
    // x layout: (n, g, d) row-major -> vector (g, n) at ((n*Gn + g) * Dn)
    for (int i = tid; i < NTILE * 32; i += 256) {
        int n  = i & 127;
        int kv = i >> 7;              // 0..31 (float4 index along k)
        float4 v = *(const float4*)(x + ((size_t)(n0 + n) * Gn + g) * Dn + kv * 4);
        Xs[(kv * 4 + 0) * NTILE + n] = v.x;
        Xs[(kv * 4 + 1) * NTILE + n] = v.y;
        Xs[(kv * 4 + 2) * NTILE + n] = v.z;
        Xs[(kv * 4 + 3) * NTILE + n] = v.w;
    }

    float bestv[8];
    int   bestidx[8];
    #pragma unroll
    for (int i = 0; i < 8; i++) { bestv[i] = 3.4e38f; bestidx[i] = 0; }

    for (int m0 = 0; m0 < Mn; m0 += MTILE) {
        __syncthreads();
        // ---- load E tile transposed into Es[k][m] ----
        for (int i = tid; i < MTILE * 32; i += 256) {
            int m  = i & 127;
            int kv = i >> 7;
            float4 v = *(const float4*)(emb + ((size_t)g * Mn + m0 + m) * Dn + kv * 4);
            Es[(kv * 4 + 0) * MTILE + m] = v.x;
            Es[(kv * 4 + 1) * MTILE + m] = v.y;
            Es[(kv * 4 + 2) * MTILE + m] = v.z;
            Es[(kv * 4 + 3) * MTILE + m] = v.w;
        }
        __syncthreads();

        float acc[8][8];
        #pragma unroll
        for (int i = 0; i < 8; i++)
            #pragma unroll
            for (int j = 0; j < 8; j++) acc[i][j] = 0.0f;

        #pragma unroll 4
        for (int k = 0; k < Dn; k++) {
            float a[8], b[8];
            *(float4*)(a)     = *(const float4*)(Xs + k * NTILE + ty * 8);
            *(float4*)(a + 4) = *(const float4*)(Xs + k * NTILE + ty * 8 + 4);
            *(float4*)(b)     = *(const float4*)(Es + k * MTILE + tx * 8);
            *(float4*)(b + 4) = *(const float4*)(Es + k * MTILE + tx * 8 + 4);
            #pragma unroll
            for (int i = 0; i < 8; i++)
                #pragma unroll
                for (int j = 0; j < 8; j++)
                    acc[i][j] = fmaf(a[i], b[j], acc[i][j]);
        }

        // ---- argmin epilogue: score = e2 - 2*dot (x^2 is row-constant) ----
        #pragma unroll
        for (int j = 0; j < 8; j++) {
            int   midx = m0 + tx * 8 + j;
            float e2   = g_e2[g * Mn + midx];
            #pragma unroll
            for (int i = 0; i < 8; i++) {
                float s = fmaf(-2.0f, acc[i][j], e2);
                if (s < bestv[i]) { bestv[i] = s; bestidx[i] = midx; }
            }
        }
    }
    __syncthreads();

    // ---- cross-thread reduction (16 candidates per row), reuse Xs ----
    float* rv = Xs;                           // [128][16]
    int*   ri = (int*)(Xs + NTILE * 16);      // [128][16]
    #pragma unroll
    for (int i = 0; i < 8; i++) {
        rv[(ty * 8 + i) * 16 + tx] = bestv[i];
        ri[(ty * 8 + i) * 16 + tx] = bestidx[i];
    }
    __syncthreads();

    if (tid < NTILE) {
        int row = tid;
        float bv = rv[row * 16];
        int   bi = ri[row * 16];
        #pragma unroll
        for (int t = 1; t < 16; t++) {
            float v  = rv[row * 16 + t];
            int   id = ri[row * 16 + t];
            if (v < bv || (v == bv && id < bi)) { bv = v; bi = id; }
        }
        winner[row] = bi;
        int nglob = n0 + row;
        out[IND_BASE + (size_t)nglob * Gn + g] = (float)bi;          // index
        atomicAdd(&out[CNT_BASE + g * Mn + bi], 1.0f);               // histogram
    }
    __syncthreads();

    // ---- gather x_quant: copy winning embedding rows (coalesced) ----
    for (int i = tid; i < NTILE * 32; i += 256) {
        int row = i >> 5;
        int c4  = i & 31;
        int bi  = winner[row];
        float4 v = *(const float4*)(emb + ((size_t)g * Mn + bi) * Dn + c4 * 4);
        *(float4*)(out + ((size_t)(n0 + row) * Gn + g) * Dn + c4 * 4) = v;
    }
}

// ---------------------------------------------------------------------------
extern "C" void kernel_launch(void* const* d_in, const int* in_sizes, int n_in,
                              void* d_out, int out_size) {
    const float* x     = (const float*)d_in[0];
    const float* emb   = (const float*)d_in[1];
    const float* count = (const float*)d_in[2];
    float*       out   = (float*)d_out;

    const int smem_bytes = 2 * Dn * NTILE * (int)sizeof(float);   // 128 KB
    cudaFuncSetAttribute(vq_kernel,
                         cudaFuncAttributeMaxDynamicSharedMemorySize, smem_bytes);

    // prep: 16384 warps (one per embedding row) + count copy
    prep_kernel<<<(Gn * Mn * 32 + 255) / 256, 256>>>(emb, count, out);

    dim3 grid(NPG / NTILE, Gn);
    vq_kernel<<<grid, 256, smem_bytes>>>(x, emb, out);
}

// round 6
// speedup vs baseline: 1.6447x; 1.6415x over previous
#include <cuda_runtime.h>
#include <cuda_bf16.h>
#include <cstdint>
#include <float.h>

// ---------------- problem constants ----------------
#define Gn    4
#define Mn    4096
#define Dn    128
#define NPG   16384
#define NTILE 128              // queries per CTA
#define BM    64               // codes per streamed B tile
#define NT    (Mn / BM)        // 64 tiles
#define TK    384              // split-K (hi|hi|lo) x (hi|lo|hi)
#define KCH   (TK / 16)        // 24 k-steps of 16

#define XQ_SIZE  (NPG * Gn * Dn)
#define IND_BASE (XQ_SIZE)
#define CNT_BASE (XQ_SIZE + NPG * Gn)

// ---------------- device scratch (allocation-free) ----------------
__device__ float          g_e2[Gn * Mn];
__device__ int            g_idx[NPG * Gn];
__device__ __nv_bfloat16  g_Xs[(size_t)NPG * Gn * TK];   // [g*16384+n][384]  (-2x: hi|hi|lo)
__device__ __nv_bfloat16  g_Es[(size_t)Gn * Mn * TK];    // [g*4096+m][384]   (e:  hi|lo|hi)

// ---------------- smem layout (dynamic) ----------------
#define A_OFF   0               // 96 KB : 24 chunks x 128 rows x 32B
#define B_OFF0  98304           // 48 KB : 24 chunks x  64 rows x 32B
#define B_OFF1  147456          // 48 KB
#define E2_OFF  196608          // 2 x 64 floats
#define SMEM_TOTAL 197120

// ---------------- PTX helpers ----------------
__device__ __forceinline__ uint32_t smem_u32(const void* p) {
    uint32_t a;
    asm("{ .reg .u64 t; cvta.to.shared.u64 t, %1; cvt.u32.u64 %0, t; }" : "=r"(a) : "l"(p));
    return a;
}
__device__ __forceinline__ void ldsm_x4(uint32_t& r0, uint32_t& r1, uint32_t& r2, uint32_t& r3,
                                        uint32_t a) {
    asm volatile("ldmatrix.sync.aligned.m8n8.x4.shared.b16 {%0,%1,%2,%3}, [%4];"
                 : "=r"(r0), "=r"(r1), "=r"(r2), "=r"(r3) : "r"(a));
}
__device__ __forceinline__ void mma16816(float* d, uint32_t a0, uint32_t a1, uint32_t a2,
                                         uint32_t a3, uint32_t b0, uint32_t b1) {
    asm volatile("mma.sync.aligned.m16n8k16.row.col.f32.bf16.bf16.f32 "
                 "{%0,%1,%2,%3}, {%4,%5,%6,%7}, {%8,%9}, {%0,%1,%2,%3};"
                 : "+f"(d[0]), "+f"(d[1]), "+f"(d[2]), "+f"(d[3])
                 : "r"(a0), "r"(a1), "r"(a2), "r"(a3), "r"(b0), "r"(b1));
}
__device__ __forceinline__ void cp16(uint32_t dst, const void* src) {
    asm volatile("cp.async.cg.shared.global [%0], [%1], 16;" :: "r"(dst), "l"(src));
}
__device__ __forceinline__ void cp4(uint32_t dst, const void* src) {
    asm volatile("cp.async.ca.shared.global [%0], [%1], 4;" :: "r"(dst), "l"(src));
}
#define CP_COMMIT() asm volatile("cp.async.commit_group;" ::: "memory")
#define CP_WAIT1()  asm volatile("cp.async.wait_group 1;" ::: "memory")

// ---------------------------------------------------------------------------
// prep: split X (-2x) and E into bf16 hi/lo, compute e2, copy count.
// ---------------------------------------------------------------------------
__device__ __forceinline__ uint32_t pack_bf2(float a, float b) {
    __nv_bfloat162 h = __floats2bfloat162_rn(a, b);
    return *(uint32_t*)&h;
}

__global__ void prep_kernel(const float* __restrict__ x,
                            const float* __restrict__ emb,
                            const float* __restrict__ count,
                            float* __restrict__ out) {
    int gt   = blockIdx.x * blockDim.x + threadIdx.x;
    int w    = gt >> 5;
    int lane = gt & 31;
    if (gt < Gn * Mn) out[CNT_BASE + gt] = count[gt];

    if (w < NPG * Gn) {                       // ---- X rows: -2x split (hi|hi|lo) ----
        int g = w >> 14, n = w & (NPG - 1);
        float4 v = ((const float4*)(x + ((size_t)n * Gn + g) * Dn))[lane];
        float a0 = -2.f * v.x, a1 = -2.f * v.y, a2 = -2.f * v.z, a3 = -2.f * v.w;
        float h0 = __bfloat162float(__float2bfloat16_rn(a0));
        float h1 = __bfloat162float(__float2bfloat16_rn(a1));
        float h2 = __bfloat162float(__float2bfloat16_rn(a2));
        float h3 = __bfloat162float(__float2bfloat16_rn(a3));
        uint2 hi; hi.x = pack_bf2(a0, a1); hi.y = pack_bf2(a2, a3);
        uint2 lo; lo.x = pack_bf2(a0 - h0, a1 - h1); lo.y = pack_bf2(a2 - h2, a3 - h3);
        __nv_bfloat16* row = g_Xs + (size_t)w * TK;
        ((uint2*)row)[lane]         = hi;
        ((uint2*)(row + 128))[lane] = hi;
        ((uint2*)(row + 256))[lane] = lo;
    } else if (w < NPG * Gn + Gn * Mn) {      // ---- E rows: split (hi|lo|hi) + e2 ----
        int r = w - NPG * Gn;
        float4 v = ((const float4*)(emb + (size_t)r * Dn))[lane];
        float s = v.x * v.x + v.y * v.y + v.z * v.z + v.w * v.w;
        #pragma unroll
        for (int o = 16; o; o >>= 1) s += __shfl_xor_sync(0xffffffffu, s, o);
        if (lane == 0) g_e2[r] = s;
        float h0 = __bfloat162float(__float2bfloat16_rn(v.x));
        float h1 = __bfloat162float(__float2bfloat16_rn(v.y));
        float h2 = __bfloat162float(__float2bfloat16_rn(v.z));
        float h3 = __bfloat162float(__float2bfloat16_rn(v.w));
        uint2 hi; hi.x = pack_bf2(v.x, v.y);  hi.y = pack_bf2(v.z, v.w);
        uint2 lo; lo.x = pack_bf2(v.x - h0, v.y - h1); lo.y = pack_bf2(v.z - h2, v.w - h3);
        __nv_bfloat16* row = g_Es + (size_t)r * TK;
        ((uint2*)row)[lane]         = hi;
        ((uint2*)(row + 128))[lane] = lo;
        ((uint2*)(row + 256))[lane] = hi;
    }
}

// ---------------------------------------------------------------------------
// vq: HMMA (mma.sync bf16) GEMM with fused top-2 argmin epilogue.
// CTA = (g, 128-query tile). A (128x384) resident in smem; B streamed in
// 64-code tiles, cp.async double-buffered. Warps 2x4; warp tile 64q x 16c.
// ---------------------------------------------------------------------------
__global__ __launch_bounds__(256, 1)
void vq_kernel(const float* __restrict__ x, const float* __restrict__ emb) {
    extern __shared__ char sm[];
    const uint32_t sb   = smem_u32(sm);
    const int tid  = threadIdx.x;
    const int lane = tid & 31;
    const int wid  = tid >> 5;
    const int wrow = wid >> 2;              // 0..1  (query half)
    const int wcol = wid & 3;               // 0..3  (code  slice)
    const int g    = blockIdx.y;
    const int n0   = blockIdx.x * NTILE;

    // ---- A load (row-fast mapping: conflict-free STS, L1-friendly LDG) ----
    {
        const uint4* Asrc = (const uint4*)(g_Xs + ((size_t)g * NPG + n0) * TK);
        #pragma unroll
        for (int it = 0; it < 24; it++) {
            int ch = tid + it * 256;           // 6144 x 16B
            int r = ch & 127, j = ch >> 7;     // j 0..47
            uint4 v = Asrc[(size_t)r * 48 + j];
            int c = j >> 1, h = j & 1;
            uint32_t off = c * 4096 + r * 32 + ((h * 16) ^ ((r & 4) ? 16 : 0));
            *(uint4*)(sm + A_OFF + off) = v;
        }
    }

    const uint4* Bsrc = (const uint4*)(g_Es + (size_t)g * Mn * TK);
    auto load_B = [&](int t) {
        const uint32_t boff = (t & 1) ? B_OFF1 : B_OFF0;
        const int m0 = t * BM;
        #pragma unroll
        for (int it = 0; it < 12; it++) {
            int ch = tid + it * 256;           // 3072 x 16B (gmem-coalesced)
            int r = ch / 48, j = ch % 48;
            int c = j >> 1, h = j & 1;
            uint32_t dst = sb + boff + c * 2048 + r * 32 + ((h * 16) ^ ((r & 4) ? 16 : 0));
            cp16(dst, Bsrc + (size_t)(m0 + r) * 48 + j);
        }
        if (tid < BM) cp4(sb + E2_OFF + (t & 1) * 256 + tid * 4, g_e2 + g * Mn + m0 + tid);
    };

    // ---- per-lane ldmatrix addresses ----
    const int lr  = (lane & 7) + ((lane >> 3) & 1) * 8;   // row-in-16
    const int lkh = lane >> 4;                            // k half (0/1)
    uint32_t a_addr[4];
    #pragma unroll
    for (int i = 0; i < 4; i++) {
        int ar = wrow * 64 + i * 16 + lr;
        a_addr[i] = sb + A_OFF + ar * 32 + ((lkh * 16) ^ ((ar & 4) ? 16 : 0));
    }
    const int br = wcol * 16 + lr;
    const uint32_t b_off = br * 32 + ((lkh * 16) ^ ((br & 4) ? 16 : 0));

    float v1[8], v2[8];
    int   i1[8], i2[8];
    #pragma unroll
    for (int s = 0; s < 8; s++) { v1[s] = FLT_MAX; v2[s] = FLT_MAX; i1[s] = 0; i2[s] = 0; }

    load_B(0); CP_COMMIT();
    __syncthreads();                         // A visible to all warps

    for (int t = 0; t < NT; t++) {
        if (t + 1 < NT) load_B(t + 1);
        CP_COMMIT();
        CP_WAIT1();
        __syncthreads();                     // tile t resident everywhere

        const uint32_t bbase = sb + ((t & 1) ? B_OFF1 : B_OFF0) + b_off;
        float acc[4][2][4];
        #pragma unroll
        for (int i = 0; i < 4; i++)
            #pragma unroll
            for (int j = 0; j < 2; j++)
                #pragma unroll
                for (int e = 0; e < 4; e++) acc[i][j][e] = 0.0f;

        #pragma unroll
        for (int ks = 0; ks < KCH; ks++) {
            uint32_t b0, b1, b2, b3;
            ldsm_x4(b0, b1, b2, b3, bbase + ks * 2048);
            #pragma unroll
            for (int i = 0; i < 4; i++) {
                uint32_t a0, a1, a2, a3;
                ldsm_x4(a0, a1, a2, a3, a_addr[i] + ks * 4096);
                mma16816(acc[i][0], a0, a1, a2, a3, b0, b2);
                mma16816(acc[i][1], a0, a1, a2, a3, b1, b3);
            }
        }

        // ---- epilogue: score = e2 + (-2 dot); top-2 per row-slot ----
        const float* e2s = (const float*)(sm + E2_OFF + (t & 1) * 256);
        const int mbase = t * BM;
        #pragma unroll
        for (int j = 0; j < 2; j++) {
            int c0 = wcol * 16 + j * 8 + (lane & 3) * 2;
            float ea = e2s[c0], eb = e2s[c0 + 1];
            int ia = mbase + c0, ib = mbase + c0 + 1;
            #pragma unroll
            for (int i = 0; i < 4; i++) {
                #pragma unroll
                for (int rh = 0; rh < 2; rh++) {
                    int s = i * 2 + rh;
                    float s0 = acc[i][j][rh * 2 + 0] + ea;
                    float s1 = acc[i][j][rh * 2 + 1] + eb;
                    if (s0 < v1[s])      { v2[s] = v1[s]; i2[s] = i1[s]; v1[s] = s0; i1[s] = ia; }
                    else if (s0 < v2[s]) { v2[s] = s0; i2[s] = ia; }
                    if (s1 < v1[s])      { v2[s] = v1[s]; i2[s] = i1[s]; v1[s] = s1; i1[s] = ib; }
                    else if (s1 < v2[s]) { v2[s] = s1; i2[s] = ib; }
                }
            }
        }
        __syncthreads();                     // done with buf before overwrite
    }

    // ---- cross-lane/warp reduction (reuse B buffer 0) ----
    float4* red = (float4*)(sm + B_OFF0);    // [128 rows][16 slots]
    #pragma unroll
    for (int s = 0; s < 8; s++) {
        int row  = wrow * 64 + (s >> 1) * 16 + (s & 1) * 8 + (lane >> 2);
        int slot = wcol * 4 + (lane & 3);
        red[row * 16 + slot] =
            make_float4(v1[s], __int_as_float(i1[s]), v2[s], __int_as_float(i2[s]));
    }
    __syncthreads();

    if (tid < NTILE) {
        float bv1 = FLT_MAX, bv2 = FLT_MAX;
        int   bi1 = 0, bi2 = 0;
        #pragma unroll 4
        for (int q = 0; q < 16; q++) {
            float4 c = red[tid * 16 + q];
            float v = c.x; int id = __float_as_int(c.y);
            if (v < bv1 || (v == bv1 && id < bi1)) { bv2 = bv1; bi2 = bi1; bv1 = v; bi1 = id; }
            else if (v < bv2 || (v == bv2 && id < bi2)) { bv2 = v; bi2 = id; }
            v = c.z; id = __float_as_int(c.w);
            if (v < bv1 || (v == bv1 && id < bi1)) { bv2 = bv1; bi2 = bi1; bv1 = v; bi1 = id; }
            else if (v < bv2 || (v == bv2 && id < bi2)) { bv2 = v; bi2 = id; }
        }
        const int n = n0 + tid;
        if (bv2 - bv1 < 4e-3f) {             // exact fp32 rescore when close
            const float* xr = x   + ((size_t)n * Gn + g) * Dn;
            const float* ea = emb + ((size_t)(g * Mn + bi1)) * Dn;
            const float* eb = emb + ((size_t)(g * Mn + bi2)) * Dn;
            float da = 0.f, db = 0.f;
            #pragma unroll 8
            for (int k = 0; k < Dn; k += 4) {
                float4 xv = *(const float4*)(xr + k);
                float4 va = *(const float4*)(ea + k);
                float4 vb = *(const float4*)(eb + k);
                da = fmaf(xv.x, va.x, fmaf(xv.y, va.y, fmaf(xv.z, va.z, fmaf(xv.w, va.w, da))));
                db = fmaf(xv.x, vb.x, fmaf(xv.y, vb.y, fmaf(xv.z, vb.z, fmaf(xv.w, vb.w, db))));
            }
            float s1 = fmaf(-2.f, da, g_e2[g * Mn + bi1]);
            float s2 = fmaf(-2.f, db, g_e2[g * Mn + bi2]);
            if (s2 < s1 || (s2 == s1 && bi2 < bi1)) bi1 = bi2;
        }
        g_idx[(size_t)n * Gn + g] = bi1;
    }
}

// ---------------------------------------------------------------------------
// gather + histogram + index write (one warp per (n,g) row)
// ---------------------------------------------------------------------------
__global__ void gather_kernel(const float* __restrict__ emb,
                              float* __restrict__ out) {
    int w    = (blockIdx.x * blockDim.x + threadIdx.x) >> 5;
    int lane = threadIdx.x & 31;
    if (w >= NPG * Gn) return;
    int g  = w & 3;
    int bi = g_idx[w];
    const float4* src = (const float4*)(emb + ((size_t)(g * Mn + bi)) * Dn);
    ((float4*)(out + (size_t)w * Dn))[lane] = src[lane];
    if (lane == 0) {
        out[IND_BASE + w] = (float)bi;
        atomicAdd(&out[CNT_BASE + g * Mn + bi], 1.0f);
    }
}

// ---------------------------------------------------------------------------
extern "C" void kernel_launch(void* const* d_in, const int* in_sizes, int n_in,
                              void* d_out, int out_size) {
    const float* x     = (const float*)d_in[0];
    const float* emb   = (const float*)d_in[1];
    const float* count = (const float*)d_in[2];
    float*       out   = (float*)d_out;

    cudaFuncSetAttribute(vq_kernel,
                         cudaFuncAttributeMaxDynamicSharedMemorySize, SMEM_TOTAL);

    prep_kernel<<<(NPG * Gn + Gn * Mn) * 32 / 256, 256>>>(x, emb, count, out);

    dim3 grid(NPG / NTILE, Gn);
    vq_kernel<<<grid, 256, SMEM_TOTAL>>>(x, emb);

    gather_kernel<<<(NPG * Gn * 32) / 256, 256>>>(emb, out);
}

// round 7
// speedup vs baseline: 2.0865x; 1.2686x over previous
#include <cuda_runtime.h>
#include <cuda_bf16.h>
#include <cstdint>
#include <float.h>

// ---------------- problem constants ----------------
#define Gn    4
#define Mn    4096
#define Dn    128
#define NPG   16384
#define NTILE 128              // queries per CTA
#define BM    128              // codes per streamed B tile
#define NT    (Mn / BM)        // 32 tiles
#define TKU   256              // unique split width: hi(128) | lo(128)

#define XQ_SIZE  (NPG * Gn * Dn)
#define IND_BASE (XQ_SIZE)
#define CNT_BASE (XQ_SIZE + NPG * Gn)

// ---------------- device scratch (allocation-free) ----------------
__device__ float          g_e2[Gn * Mn];
__device__ int            g_idx[NPG * Gn];
__device__ __nv_bfloat16  g_Xs[(size_t)NPG * Gn * TKU];  // -2x: [hi(128) | lo(128)]
__device__ __nv_bfloat16  g_Es[(size_t)Gn * Mn * TKU];   //  e : [hi(128) | lo(128)]

// ---------------- smem layout (dynamic) ----------------
// chunk = one k16 slice: 128 rows x 32B = 4096 B.  16 chunks (8 hi + 8 lo).
#define A_OFF   0               // 64 KB
#define B_OFF0  65536           // 64 KB
#define B_OFF1  131072          // 64 KB
#define E2_OFF  196608          // 2 x 128 floats
#define SMEM_TOTAL 197632

// ---------------- PTX helpers ----------------
__device__ __forceinline__ uint32_t smem_u32(const void* p) {
    uint32_t a;
    asm("{ .reg .u64 t; cvta.to.shared.u64 t, %1; cvt.u32.u64 %0, t; }" : "=r"(a) : "l"(p));
    return a;
}
__device__ __forceinline__ void ldsm_x4(uint32_t* r, uint32_t a) {
    asm volatile("ldmatrix.sync.aligned.m8n8.x4.shared.b16 {%0,%1,%2,%3}, [%4];"
                 : "=r"(r[0]), "=r"(r[1]), "=r"(r[2]), "=r"(r[3]) : "r"(a));
}
__device__ __forceinline__ void mma16816(float* d, const uint32_t* a, uint32_t b0, uint32_t b1) {
    asm volatile("mma.sync.aligned.m16n8k16.row.col.f32.bf16.bf16.f32 "
                 "{%0,%1,%2,%3}, {%4,%5,%6,%7}, {%8,%9}, {%0,%1,%2,%3};"
                 : "+f"(d[0]), "+f"(d[1]), "+f"(d[2]), "+f"(d[3])
                 : "r"(a[0]), "r"(a[1]), "r"(a[2]), "r"(a[3]), "r"(b0), "r"(b1));
}
__device__ __forceinline__ void cp16(uint32_t dst, const void* src) {
    asm volatile("cp.async.cg.shared.global [%0], [%1], 16;" :: "r"(dst), "l"(src));
}
__device__ __forceinline__ void cp4(uint32_t dst, const void* src) {
    asm volatile("cp.async.ca.shared.global [%0], [%1], 4;" :: "r"(dst), "l"(src));
}
#define CP_COMMIT() asm volatile("cp.async.commit_group;" ::: "memory")
#define CP_WAIT0()  asm volatile("cp.async.wait_group 0;" ::: "memory")

// ---------------------------------------------------------------------------
// prep: split X (-2x) and E into bf16 hi|lo (dedup), e2, count copy.
// ---------------------------------------------------------------------------
__device__ __forceinline__ uint32_t pack_bf2(float a, float b) {
    __nv_bfloat162 h = __floats2bfloat162_rn(a, b);
    return *(uint32_t*)&h;
}

__global__ void prep_kernel(const float* __restrict__ x,
                            const float* __restrict__ emb,
                            const float* __restrict__ count,
                            float* __restrict__ out) {
    int gt   = blockIdx.x * blockDim.x + threadIdx.x;
    int w    = gt >> 5;
    int lane = gt & 31;
    if (gt < Gn * Mn) out[CNT_BASE + gt] = count[gt];

    if (w < NPG * Gn) {                       // ---- X rows: -2x split ----
        int g = w >> 14, n = w & (NPG - 1);
        float4 v = ((const float4*)(x + ((size_t)n * Gn + g) * Dn))[lane];
        float a0 = -2.f * v.x, a1 = -2.f * v.y, a2 = -2.f * v.z, a3 = -2.f * v.w;
        float h0 = __bfloat162float(__float2bfloat16_rn(a0));
        float h1 = __bfloat162float(__float2bfloat16_rn(a1));
        float h2 = __bfloat162float(__float2bfloat16_rn(a2));
        float h3 = __bfloat162float(__float2bfloat16_rn(a3));
        uint2 hi; hi.x = pack_bf2(a0, a1); hi.y = pack_bf2(a2, a3);
        uint2 lo; lo.x = pack_bf2(a0 - h0, a1 - h1); lo.y = pack_bf2(a2 - h2, a3 - h3);
        __nv_bfloat16* row = g_Xs + (size_t)w * TKU;
        ((uint2*)row)[lane]         = hi;
        ((uint2*)(row + 128))[lane] = lo;
    } else if (w < NPG * Gn + Gn * Mn) {      // ---- E rows: split + e2 ----
        int r = w - NPG * Gn;
        float4 v = ((const float4*)(emb + (size_t)r * Dn))[lane];
        float s = v.x * v.x + v.y * v.y + v.z * v.z + v.w * v.w;
        #pragma unroll
        for (int o = 16; o; o >>= 1) s += __shfl_xor_sync(0xffffffffu, s, o);
        if (lane == 0) g_e2[r] = s;
        float h0 = __bfloat162float(__float2bfloat16_rn(v.x));
        float h1 = __bfloat162float(__float2bfloat16_rn(v.y));
        float h2 = __bfloat162float(__float2bfloat16_rn(v.z));
        float h3 = __bfloat162float(__float2bfloat16_rn(v.w));
        uint2 hi; hi.x = pack_bf2(v.x, v.y);  hi.y = pack_bf2(v.z, v.w);
        uint2 lo; lo.x = pack_bf2(v.x - h0, v.y - h1); lo.y = pack_bf2(v.z - h2, v.w - h3);
        __nv_bfloat16* row = g_Es + (size_t)r * TKU;
        ((uint2*)row)[lane]         = hi;
        ((uint2*)(row + 128))[lane] = lo;
    }
}

// ---------------------------------------------------------------------------
// vq: HMMA GEMM, 3 split terms fused into one accumulator.
// 16 warps (4x4 grid), warp tile 32q x 32c; BM=128 double-buffered, 1 sync/tile.
// ---------------------------------------------------------------------------
__global__ __launch_bounds__(512, 1)
void vq_kernel(const float* __restrict__ x, const float* __restrict__ emb) {
    extern __shared__ char sm[];
    const uint32_t sb   = smem_u32(sm);
    const int tid  = threadIdx.x;
    const int lane = tid & 31;
    const int wid  = tid >> 5;
    const int wrow = wid >> 2;              // 0..3  (32-query band)
    const int wcol = wid & 3;               // 0..3  (32-code band)
    const int g    = blockIdx.y;
    const int n0   = blockIdx.x * NTILE;

    // ---- A load (once): 4096 x 16B chunks, validated r-fast mapping ----
    {
        const uint4* Asrc = (const uint4*)(g_Xs + ((size_t)g * NPG + n0) * TKU);
        #pragma unroll
        for (int it = 0; it < 8; it++) {
            int ch = tid + it * 512;
            int r = ch & 127, j = ch >> 7;     // j 0..31
            uint4 v = Asrc[(size_t)r * 32 + j];
            int c = j >> 1, h = j & 1;
            uint32_t off = c * 4096 + r * 32 + ((h * 16) ^ ((r & 4) ? 16 : 0));
            *(uint4*)(sm + A_OFF + off) = v;
        }
    }

    const uint4* Bsrc = (const uint4*)(g_Es + (size_t)g * Mn * TKU);
    auto load_B = [&](int t) {
        const uint32_t boff = (t & 1) ? B_OFF1 : B_OFF0;
        const int m0 = t * BM;
        #pragma unroll
        for (int it = 0; it < 8; it++) {
            int ch = tid + it * 512;           // 4096 x 16B, gmem-coalesced
            int r = ch >> 5, j = ch & 31;
            int c = j >> 1, h = j & 1;
            uint32_t dst = sb + boff + c * 4096 + r * 32 + ((h * 16) ^ ((r & 4) ? 16 : 0));
            cp16(dst, Bsrc + (size_t)(m0 + r) * 32 + j);
        }
        if (tid < BM) cp4(sb + E2_OFF + (t & 1) * 512 + tid * 4, g_e2 + g * Mn + m0 + tid);
    };

    // ---- per-lane ldmatrix addresses ----
    const int lr  = (lane & 7) + ((lane >> 3) & 1) * 8;   // row-in-16
    const int lkh = lane >> 4;                            // k half (0/1)
    uint32_t a_base[2];
    #pragma unroll
    for (int i = 0; i < 2; i++) {
        int ar = wrow * 32 + i * 16 + lr;
        a_base[i] = sb + A_OFF + ar * 32 + ((lkh * 16) ^ ((ar & 4) ? 16 : 0));
    }
    uint32_t b_off[2];
    #pragma unroll
    for (int f = 0; f < 2; f++) {
        int bc = wcol * 32 + f * 16 + lr;
        b_off[f] = bc * 32 + ((lkh * 16) ^ ((bc & 4) ? 16 : 0));
    }

    float v1[4], v2[4];
    int   i1[4], i2[4];
    #pragma unroll
    for (int s = 0; s < 4; s++) { v1[s] = FLT_MAX; v2[s] = FLT_MAX; i1[s] = 0; i2[s] = 0; }

    load_B(0); CP_COMMIT();

    for (int t = 0; t < NT; t++) {
        CP_WAIT0();
        __syncthreads();                 // tile t resident; prev buffer free
        if (t + 1 < NT) { load_B(t + 1); CP_COMMIT(); }

        const uint32_t bb = sb + ((t & 1) ? B_OFF1 : B_OFF0);
        float acc[2][4][4];
        #pragma unroll
        for (int i = 0; i < 2; i++)
            #pragma unroll
            for (int j = 0; j < 4; j++)
                #pragma unroll
                for (int e = 0; e < 4; e++) acc[i][j][e] = 0.0f;

        #pragma unroll
        for (int ks = 0; ks < 8; ks++) {
            uint32_t ah[2][4], al[2][4], bh[2][4], bl[2][4];
            #pragma unroll
            for (int i = 0; i < 2; i++) {
                ldsm_x4(ah[i], a_base[i] + ks * 4096);
                ldsm_x4(al[i], a_base[i] + (8 + ks) * 4096);
            }
            #pragma unroll
            for (int f = 0; f < 2; f++) {
                ldsm_x4(bh[f], bb + b_off[f] + ks * 4096);
                ldsm_x4(bl[f], bb + b_off[f] + (8 + ks) * 4096);
            }
            #pragma unroll
            for (int i = 0; i < 2; i++)
                #pragma unroll
                for (int f = 0; f < 2; f++) {
                    mma16816(acc[i][f * 2 + 0], ah[i], bh[f][0], bh[f][2]);  // hi*hi
                    mma16816(acc[i][f * 2 + 1], ah[i], bh[f][1], bh[f][3]);
                    mma16816(acc[i][f * 2 + 0], ah[i], bl[f][0], bl[f][2]);  // hi*lo
                    mma16816(acc[i][f * 2 + 1], ah[i], bl[f][1], bl[f][3]);
                    mma16816(acc[i][f * 2 + 0], al[i], bh[f][0], bh[f][2]);  // lo*hi
                    mma16816(acc[i][f * 2 + 1], al[i], bh[f][1], bh[f][3]);
                }
        }

        // ---- epilogue: score = e2 + (-2 dot); top-2 per row-slot ----
        const float* e2s = (const float*)(sm + E2_OFF + (t & 1) * 512);
        const int mbase = t * BM;
        #pragma unroll
        for (int jf = 0; jf < 4; jf++) {
            int c0 = wcol * 32 + (jf >> 1) * 16 + (jf & 1) * 8 + (lane & 3) * 2;
            float ea = e2s[c0], eb = e2s[c0 + 1];
            int ia = mbase + c0, ib = ia + 1;
            #pragma unroll
            for (int i = 0; i < 2; i++)
                #pragma unroll
                for (int rh = 0; rh < 2; rh++) {
                    int s = i * 2 + rh;
                    float s0 = acc[i][jf][rh * 2 + 0] + ea;
                    float s1 = acc[i][jf][rh * 2 + 1] + eb;
                    if (s0 < v1[s])      { v2[s] = v1[s]; i2[s] = i1[s]; v1[s] = s0; i1[s] = ia; }
                    else if (s0 < v2[s]) { v2[s] = s0; i2[s] = ia; }
                    if (s1 < v1[s])      { v2[s] = v1[s]; i2[s] = i1[s]; v1[s] = s1; i1[s] = ib; }
                    else if (s1 < v2[s]) { v2[s] = s1; i2[s] = ib; }
                }
        }
    }

    // ---- cross-lane/warp reduction (reuse B buffer 0; tile 31 used buf 1) ----
    float4* red = (float4*)(sm + B_OFF0);    // [128 rows][16 slots]
    #pragma unroll
    for (int s = 0; s < 4; s++) {
        int row  = wrow * 32 + (s >> 1) * 16 + (s & 1) * 8 + (lane >> 2);
        int slot = wcol * 4 + (lane & 3);
        red[row * 16 + slot] =
            make_float4(v1[s], __int_as_float(i1[s]), v2[s], __int_as_float(i2[s]));
    }
    __syncthreads();

    if (tid < NTILE) {
        float bv1 = FLT_MAX, bv2 = FLT_MAX;
        int   bi1 = 0, bi2 = 0;
        #pragma unroll 4
        for (int q = 0; q < 16; q++) {
            float4 c = red[tid * 16 + q];
            float v = c.x; int id = __float_as_int(c.y);
            if (v < bv1 || (v == bv1 && id < bi1)) { bv2 = bv1; bi2 = bi1; bv1 = v; bi1 = id; }
            else if (v < bv2 || (v == bv2 && id < bi2)) { bv2 = v; bi2 = id; }
            v = c.z; id = __float_as_int(c.w);
            if (v < bv1 || (v == bv1 && id < bi1)) { bv2 = bv1; bi2 = bi1; bv1 = v; bi1 = id; }
            else if (v < bv2 || (v == bv2 && id < bi2)) { bv2 = v; bi2 = id; }
        }
        const int n = n0 + tid;
        if (bv2 - bv1 < 4e-3f) {             // exact fp32 rescore when close
            const float* xr = x   + ((size_t)n * Gn + g) * Dn;
            const float* ea = emb + ((size_t)(g * Mn + bi1)) * Dn;
            const float* eb = emb + ((size_t)(g * Mn + bi2)) * Dn;
            float da = 0.f, db = 0.f;
            #pragma unroll 8
            for (int k = 0; k < Dn; k += 4) {
                float4 xv = *(const float4*)(xr + k);
                float4 va = *(const float4*)(ea + k);
                float4 vb = *(const float4*)(eb + k);
                da = fmaf(xv.x, va.x, fmaf(xv.y, va.y, fmaf(xv.z, va.z, fmaf(xv.w, va.w, da))));
                db = fmaf(xv.x, vb.x, fmaf(xv.y, vb.y, fmaf(xv.z, vb.z, fmaf(xv.w, vb.w, db))));
            }
            float s1 = fmaf(-2.f, da, g_e2[g * Mn + bi1]);
            float s2 = fmaf(-2.f, db, g_e2[g * Mn + bi2]);
            if (s2 < s1 || (s2 == s1 && bi2 < bi1)) bi1 = bi2;
        }
        g_idx[(size_t)n * Gn + g] = bi1;
    }
}

// ---------------------------------------------------------------------------
// gather + histogram + index write (one warp per (n,g) row)
// ---------------------------------------------------------------------------
__global__ void gather_kernel(const float* __restrict__ emb,
                              float* __restrict__ out) {
    int w    = (blockIdx.x * blockDim.x + threadIdx.x) >> 5;
    int lane = threadIdx.x & 31;
    if (w >= NPG * Gn) return;
    int g  = w & 3;
    int bi = g_idx[w];
    const float4* src = (const float4*)(emb + ((size_t)(g * Mn + bi)) * Dn);
    ((float4*)(out + (size_t)w * Dn))[lane] = src[lane];
    if (lane == 0) {
        out[IND_BASE + w] = (float)bi;
        atomicAdd(&out[CNT_BASE + g * Mn + bi], 1.0f);
    }
}

// ---------------------------------------------------------------------------
extern "C" void kernel_launch(void* const* d_in, const int* in_sizes, int n_in,
                              void* d_out, int out_size) {
    const float* x     = (const float*)d_in[0];
    const float* emb   = (const float*)d_in[1];
    const float* count = (const float*)d_in[2];
    float*       out   = (float*)d_out;

    cudaFuncSetAttribute(vq_kernel,
                         cudaFuncAttributeMaxDynamicSharedMemorySize, SMEM_TOTAL);

    prep_kernel<<<(NPG * Gn + Gn * Mn) * 32 / 256, 256>>>(x, emb, count, out);

    dim3 grid(NPG / NTILE, Gn);
    vq_kernel<<<grid, 512, SMEM_TOTAL>>>(x, emb);

    gather_kernel<<<(NPG * Gn * 32) / 256, 256>>>(emb, out);
}

// round 8
// speedup vs baseline: 3.6499x; 1.7493x over previous
#include <cuda_runtime.h>
#include <cuda_fp16.h>
#include <cstdint>
#include <float.h>

// ---------------- problem constants ----------------
#define Gn    4
#define Mn    4096
#define Dn    128
#define NPG   16384
#define NTILE 128              // queries per CTA
#define BM    128              // codes per streamed B tile
#define NT    (Mn / BM)        // 32 tiles
#define KCH   8                // 8 k16 chunks (K=128)

#define XQ_SIZE  (NPG * Gn * Dn)
#define IND_BASE (XQ_SIZE)
#define CNT_BASE (XQ_SIZE + NPG * Gn)

#define RESCUE_TAU 0.15f

// ---------------- device scratch (allocation-free) ----------------
__device__ float  g_e2[Gn * Mn];
__device__ int    g_idx[NPG * Gn];
__device__ __half g_Xs[(size_t)NPG * Gn * Dn];   // fp16(-2x)
__device__ __half g_Es[(size_t)Gn * Mn * Dn];    // fp16(e)

// ---------------- smem layout (dynamic) ----------------
// chunk = one k16 slice: 128 rows x 32B = 4096 B.  8 chunks per tile.
#define A_OFF   0               // 32 KB
#define B_OFF0  32768           // 32 KB
#define B_OFF1  65536           // 32 KB
#define E2_OFF  98304           // 2 x 128 floats
#define SMEM_TOTAL 99328

// ---------------- PTX helpers ----------------
__device__ __forceinline__ uint32_t smem_u32(const void* p) {
    uint32_t a;
    asm("{ .reg .u64 t; cvta.to.shared.u64 t, %1; cvt.u32.u64 %0, t; }" : "=r"(a) : "l"(p));
    return a;
}
__device__ __forceinline__ void ldsm_x4(uint32_t* r, uint32_t a) {
    asm volatile("ldmatrix.sync.aligned.m8n8.x4.shared.b16 {%0,%1,%2,%3}, [%4];"
                 : "=r"(r[0]), "=r"(r[1]), "=r"(r[2]), "=r"(r[3]) : "r"(a));
}
__device__ __forceinline__ void mma16816(float* d, const uint32_t* a, uint32_t b0, uint32_t b1) {
    asm volatile("mma.sync.aligned.m16n8k16.row.col.f32.f16.f16.f32 "
                 "{%0,%1,%2,%3}, {%4,%5,%6,%7}, {%8,%9}, {%0,%1,%2,%3};"
                 : "+f"(d[0]), "+f"(d[1]), "+f"(d[2]), "+f"(d[3])
                 : "r"(a[0]), "r"(a[1]), "r"(a[2]), "r"(a[3]), "r"(b0), "r"(b1));
}
__device__ __forceinline__ void cp16(uint32_t dst, const void* src) {
    asm volatile("cp.async.cg.shared.global [%0], [%1], 16;" :: "r"(dst), "l"(src));
}
__device__ __forceinline__ void cp4(uint32_t dst, const void* src) {
    asm volatile("cp.async.ca.shared.global [%0], [%1], 4;" :: "r"(dst), "l"(src));
}
#define CP_COMMIT() asm volatile("cp.async.commit_group;" ::: "memory")
#define CP_WAIT0()  asm volatile("cp.async.wait_group 0;" ::: "memory")

// ---------------------------------------------------------------------------
// prep: X -> fp16(-2x), E -> fp16(e), e2, count copy.
// ---------------------------------------------------------------------------
__device__ __forceinline__ uint32_t pack_h2(float a, float b) {
    __half2 h = __floats2half2_rn(a, b);
    return *(uint32_t*)&h;
}

__global__ void prep_kernel(const float* __restrict__ x,
                            const float* __restrict__ emb,
                            const float* __restrict__ count,
                            float* __restrict__ out) {
    int gt   = blockIdx.x * blockDim.x + threadIdx.x;
    int w    = gt >> 5;
    int lane = gt & 31;
    if (gt < Gn * Mn) out[CNT_BASE + gt] = count[gt];

    if (w < NPG * Gn) {                       // ---- X rows: fp16(-2x) ----
        int g = w >> 14, n = w & (NPG - 1);
        float4 v = ((const float4*)(x + ((size_t)n * Gn + g) * Dn))[lane];
        uint2 p;
        p.x = pack_h2(-2.f * v.x, -2.f * v.y);
        p.y = pack_h2(-2.f * v.z, -2.f * v.w);
        ((uint2*)(g_Xs + (size_t)w * Dn))[lane] = p;
    } else if (w < NPG * Gn + Gn * Mn) {      // ---- E rows: fp16 + e2 ----
        int r = w - NPG * Gn;
        float4 v = ((const float4*)(emb + (size_t)r * Dn))[lane];
        float s = v.x * v.x + v.y * v.y + v.z * v.z + v.w * v.w;
        #pragma unroll
        for (int o = 16; o; o >>= 1) s += __shfl_xor_sync(0xffffffffu, s, o);
        if (lane == 0) g_e2[r] = s;
        uint2 p;
        p.x = pack_h2(v.x, v.y);
        p.y = pack_h2(v.z, v.w);
        ((uint2*)(g_Es + (size_t)r * Dn))[lane] = p;
    }
}

// ---------------------------------------------------------------------------
// vq: single-term fp16 HMMA GEMM + top-2/thread -> top-4/row + fp32 rescue.
// 16 warps (4x4), warp tile 32q x 32c; BM=128 double-buffered, 1 sync/tile.
// ---------------------------------------------------------------------------
__global__ __launch_bounds__(512, 1)
void vq_kernel(const float* __restrict__ x, const float* __restrict__ emb) {
    extern __shared__ char sm[];
    const uint32_t sb   = smem_u32(sm);
    const int tid  = threadIdx.x;
    const int lane = tid & 31;
    const int wid  = tid >> 5;
    const int wrow = wid >> 2;              // 0..3  (32-query band)
    const int wcol = wid & 3;               // 0..3  (32-code band)
    const int g    = blockIdx.y;
    const int n0   = blockIdx.x * NTILE;

    // ---- A load (once): 2048 x 16B chunks ----
    {
        const uint4* Asrc = (const uint4*)(g_Xs + ((size_t)g * NPG + n0) * Dn);
        #pragma unroll
        for (int it = 0; it < 4; it++) {
            int ch = tid + it * 512;
            int r = ch & 127, j = ch >> 7;     // j 0..15
            uint4 v = Asrc[(size_t)r * 16 + j];
            int c = j >> 1, h = j & 1;
            uint32_t off = c * 4096 + r * 32 + ((h * 16) ^ ((r & 4) ? 16 : 0));
            *(uint4*)(sm + A_OFF + off) = v;
        }
    }

    const uint4* Bsrc = (const uint4*)(g_Es + (size_t)g * Mn * Dn);
    auto load_B = [&](int t) {
        const uint32_t boff = (t & 1) ? B_OFF1 : B_OFF0;
        const int m0 = t * BM;
        #pragma unroll
        for (int it = 0; it < 4; it++) {
            int ch = tid + it * 512;           // 2048 x 16B, gmem-coalesced
            int r = ch >> 4, j = ch & 15;
            int c = j >> 1, h = j & 1;
            uint32_t dst = sb + boff + c * 4096 + r * 32 + ((h * 16) ^ ((r & 4) ? 16 : 0));
            cp16(dst, Bsrc + (size_t)(m0 + r) * 16 + j);
        }
        if (tid < BM) cp4(sb + E2_OFF + (t & 1) * 512 + tid * 4, g_e2 + g * Mn + m0 + tid);
    };

    // ---- per-lane ldmatrix addresses ----
    const int lr  = (lane & 7) + ((lane >> 3) & 1) * 8;   // row-in-16
    const int lkh = lane >> 4;                            // k half (0/1)
    uint32_t a_base[2];
    #pragma unroll
    for (int i = 0; i < 2; i++) {
        int ar = wrow * 32 + i * 16 + lr;
        a_base[i] = sb + A_OFF + ar * 32 + ((lkh * 16) ^ ((ar & 4) ? 16 : 0));
    }
    uint32_t b_off[2];
    #pragma unroll
    for (int f = 0; f < 2; f++) {
        int bc = wcol * 32 + f * 16 + lr;
        b_off[f] = bc * 32 + ((lkh * 16) ^ ((bc & 4) ? 16 : 0));
    }

    float v1[4], v2[4];
    int   i1[4], i2[4];
    #pragma unroll
    for (int s = 0; s < 4; s++) { v1[s] = FLT_MAX; v2[s] = FLT_MAX; i1[s] = 0; i2[s] = 0; }

    load_B(0); CP_COMMIT();

    for (int t = 0; t < NT; t++) {
        CP_WAIT0();
        __syncthreads();                 // tile t resident; prev buffer free
        if (t + 1 < NT) { load_B(t + 1); CP_COMMIT(); }

        const uint32_t bb = sb + ((t & 1) ? B_OFF1 : B_OFF0);
        float acc[2][4][4];
        #pragma unroll
        for (int i = 0; i < 2; i++)
            #pragma unroll
            for (int j = 0; j < 4; j++)
                #pragma unroll
                for (int e = 0; e < 4; e++) acc[i][j][e] = 0.0f;

        #pragma unroll
        for (int ks = 0; ks < KCH; ks++) {
            uint32_t ah[2][4], bh[2][4];
            #pragma unroll
            for (int i = 0; i < 2; i++) ldsm_x4(ah[i], a_base[i] + ks * 4096);
            #pragma unroll
            for (int f = 0; f < 2; f++) ldsm_x4(bh[f], bb + b_off[f] + ks * 4096);
            #pragma unroll
            for (int i = 0; i < 2; i++)
                #pragma unroll
                for (int f = 0; f < 2; f++) {
                    mma16816(acc[i][f * 2 + 0], ah[i], bh[f][0], bh[f][2]);
                    mma16816(acc[i][f * 2 + 1], ah[i], bh[f][1], bh[f][3]);
                }
        }

        // ---- epilogue: score = e2 + (-2 dot); top-2 per row-slot ----
        const float* e2s = (const float*)(sm + E2_OFF + (t & 1) * 512);
        const int mbase = t * BM;
        #pragma unroll
        for (int jf = 0; jf < 4; jf++) {
            int c0 = wcol * 32 + (jf >> 1) * 16 + (jf & 1) * 8 + (lane & 3) * 2;
            float ea = e2s[c0], eb = e2s[c0 + 1];
            int ia = mbase + c0, ib = ia + 1;
            #pragma unroll
            for (int i = 0; i < 2; i++)
                #pragma unroll
                for (int rh = 0; rh < 2; rh++) {
                    int s = i * 2 + rh;
                    float s0 = acc[i][jf][rh * 2 + 0] + ea;
                    float s1 = acc[i][jf][rh * 2 + 1] + eb;
                    if (s0 < v1[s])      { v2[s] = v1[s]; i2[s] = i1[s]; v1[s] = s0; i1[s] = ia; }
                    else if (s0 < v2[s]) { v2[s] = s0; i2[s] = ia; }
                    if (s1 < v1[s])      { v2[s] = v1[s]; i2[s] = i1[s]; v1[s] = s1; i1[s] = ib; }
                    else if (s1 < v2[s]) { v2[s] = s1; i2[s] = ib; }
                }
        }
    }

    // ---- cross-lane/warp reduction: 16 per-thread top-2 -> row top-4 ----
    float4* red = (float4*)(sm + B_OFF0);    // [128 rows][16 slots] = 32 KB
    #pragma unroll
    for (int s = 0; s < 4; s++) {
        int row  = wrow * 32 + (s >> 1) * 16 + (s & 1) * 8 + (lane >> 2);
        int slot = wcol * 4 + (lane & 3);
        red[row * 16 + slot] =
            make_float4(v1[s], __int_as_float(i1[s]), v2[s], __int_as_float(i2[s]));
    }
    __syncthreads();

    if (tid < NTILE) {
        float tv[4] = {FLT_MAX, FLT_MAX, FLT_MAX, FLT_MAX};
        int   ti[4] = {0, 0, 0, 0};
        auto ins = [&](float v, int id) {
            if (v < tv[3] || (v == tv[3] && id < ti[3])) {
                tv[3] = v; ti[3] = id;
                #pragma unroll
                for (int k = 3; k > 0; k--)
                    if (tv[k] < tv[k-1] || (tv[k] == tv[k-1] && ti[k] < ti[k-1])) {
                        float fv = tv[k]; tv[k] = tv[k-1]; tv[k-1] = fv;
                        int   fi = ti[k]; ti[k] = ti[k-1]; ti[k-1] = fi;
                    }
            }
        };
        #pragma unroll 4
        for (int q = 0; q < 16; q++) {
            float4 c = red[tid * 16 + q];
            ins(c.x, __float_as_int(c.y));
            ins(c.z, __float_as_int(c.w));
        }
        const int n = n0 + tid;
        int best = ti[0];
        if (tv[1] - tv[0] < RESCUE_TAU) {    // exact fp32 rescore of top-4
            const float* xr = x + ((size_t)n * Gn + g) * Dn;
            float bs = FLT_MAX; int bi = 0;
            #pragma unroll
            for (int c = 0; c < 4; c++) {
                const float* er = emb + ((size_t)(g * Mn + ti[c])) * Dn;
                float d = 0.f;
                #pragma unroll 8
                for (int k = 0; k < Dn; k += 4) {
                    float4 xv = *(const float4*)(xr + k);
                    float4 ev = *(const float4*)(er + k);
                    d = fmaf(xv.x, ev.x, fmaf(xv.y, ev.y, fmaf(xv.z, ev.z, fmaf(xv.w, ev.w, d))));
                }
                float sc = fmaf(-2.f, d, g_e2[g * Mn + ti[c]]);
                if (sc < bs || (sc == bs && ti[c] < bi)) { bs = sc; bi = ti[c]; }
            }
            best = bi;
        }
        g_idx[(size_t)n * Gn + g] = best;
    }
}

// ---------------------------------------------------------------------------
// gather + histogram + index write (one warp per (n,g) row)
// ---------------------------------------------------------------------------
__global__ void gather_kernel(const float* __restrict__ emb,
                              float* __restrict__ out) {
    int w    = (blockIdx.x * blockDim.x + threadIdx.x) >> 5;
    int lane = threadIdx.x & 31;
    if (w >= NPG * Gn) return;
    int g  = w & 3;
    int bi = g_idx[w];
    const float4* src = (const float4*)(emb + ((size_t)(g * Mn + bi)) * Dn);
    ((float4*)(out + (size_t)w * Dn))[lane] = src[lane];
    if (lane == 0) {
        out[IND_BASE + w] = (float)bi;
        atomicAdd(&out[CNT_BASE + g * Mn + bi], 1.0f);
    }
}

// ---------------------------------------------------------------------------
extern "C" void kernel_launch(void* const* d_in, const int* in_sizes, int n_in,
                              void* d_out, int out_size) {
    const float* x     = (const float*)d_in[0];
    const float* emb   = (const float*)d_in[1];
    const float* count = (const float*)d_in[2];
    float*       out   = (float*)d_out;

    cudaFuncSetAttribute(vq_kernel,
                         cudaFuncAttributeMaxDynamicSharedMemorySize, SMEM_TOTAL);

    prep_kernel<<<(NPG * Gn + Gn * Mn) * 32 / 256, 256>>>(x, emb, count, out);

    dim3 grid(NPG / NTILE, Gn);
    vq_kernel<<<grid, 512, SMEM_TOTAL>>>(x, emb);

    gather_kernel<<<(NPG * Gn * 32) / 256, 256>>>(emb, out);
}

// round 9
// speedup vs baseline: 5.2244x; 1.4314x over previous
#include <cuda_runtime.h>
#include <cuda_fp16.h>
#include <cstdint>
#include <float.h>

// ---------------- problem constants ----------------
#define Gn    4
#define Mn    4096
#define Dn    128
#define NPG   16384
#define NTILE 128              // queries per CTA
#define BM    128              // codes per streamed B tile
#define NT    (Mn / BM)        // 32 tiles
#define KCH   8                // 8 k16 chunks (K=128)

#define XQ_SIZE  (NPG * Gn * Dn)
#define IND_BASE (XQ_SIZE)
#define CNT_BASE (XQ_SIZE + NPG * Gn)

#define SCORE_BIAS 512.0f      // makes scores positive (score >= -x^2 > -256)
#define RESCUE_TAU 1.0f        // covers fp16 noise + 12-bit key masking (<=0.5)

// ---------------- device scratch (allocation-free) ----------------
__device__ float  g_e2[Gn * Mn];       // exact, for rescue
__device__ float  g_e2b[Gn * Mn];      // e2 + SCORE_BIAS, for epilogue
__device__ int    g_idx[NPG * Gn];
__device__ __half g_Xs[(size_t)NPG * Gn * Dn];   // fp16(-2x)
__device__ __half g_Es[(size_t)Gn * Mn * Dn];    // fp16(e)

// ---------------- smem layout (dynamic) ----------------
#define A_OFF   0               // 32 KB
#define B_OFF0  32768           // 32 KB
#define B_OFF1  65536           // 32 KB
#define E2_OFF  98304           // 2 x 128 floats
#define SMEM_TOTAL 99328

// ---------------- PTX helpers ----------------
__device__ __forceinline__ uint32_t smem_u32(const void* p) {
    uint32_t a;
    asm("{ .reg .u64 t; cvta.to.shared.u64 t, %1; cvt.u32.u64 %0, t; }" : "=r"(a) : "l"(p));
    return a;
}
__device__ __forceinline__ void ldsm_x4(uint32_t* r, uint32_t a) {
    asm volatile("ldmatrix.sync.aligned.m8n8.x4.shared.b16 {%0,%1,%2,%3}, [%4];"
                 : "=r"(r[0]), "=r"(r[1]), "=r"(r[2]), "=r"(r[3]) : "r"(a));
}
__device__ __forceinline__ void mma16816(float* d, const uint32_t* a, uint32_t b0, uint32_t b1) {
    asm volatile("mma.sync.aligned.m16n8k16.row.col.f32.f16.f16.f32 "
                 "{%0,%1,%2,%3}, {%4,%5,%6,%7}, {%8,%9}, {%0,%1,%2,%3};"
                 : "+f"(d[0]), "+f"(d[1]), "+f"(d[2]), "+f"(d[3])
                 : "r"(a[0]), "r"(a[1]), "r"(a[2]), "r"(a[3]), "r"(b0), "r"(b1));
}
__device__ __forceinline__ void cp16(uint32_t dst, const void* src) {
    asm volatile("cp.async.cg.shared.global [%0], [%1], 16;" :: "r"(dst), "l"(src));
}
__device__ __forceinline__ void cp4(uint32_t dst, const void* src) {
    asm volatile("cp.async.ca.shared.global [%0], [%1], 4;" :: "r"(dst), "l"(src));
}
#define CP_COMMIT() asm volatile("cp.async.commit_group;" ::: "memory")
#define CP_WAIT0()  asm volatile("cp.async.wait_group 0;" ::: "memory")

// ---------------------------------------------------------------------------
// prep: X -> fp16(-2x), E -> fp16(e), e2 (raw + biased), count copy.
// ---------------------------------------------------------------------------
__device__ __forceinline__ uint32_t pack_h2(float a, float b) {
    __half2 h = __floats2half2_rn(a, b);
    return *(uint32_t*)&h;
}

__global__ void prep_kernel(const float* __restrict__ x,
                            const float* __restrict__ emb,
                            const float* __restrict__ count,
                            float* __restrict__ out) {
    int gt   = blockIdx.x * blockDim.x + threadIdx.x;
    int w    = gt >> 5;
    int lane = gt & 31;
    if (gt < Gn * Mn) out[CNT_BASE + gt] = count[gt];

    if (w < NPG * Gn) {                       // ---- X rows: fp16(-2x) ----
        int g = w >> 14, n = w & (NPG - 1);
        float4 v = ((const float4*)(x + ((size_t)n * Gn + g) * Dn))[lane];
        uint2 p;
        p.x = pack_h2(-2.f * v.x, -2.f * v.y);
        p.y = pack_h2(-2.f * v.z, -2.f * v.w);
        ((uint2*)(g_Xs + (size_t)w * Dn))[lane] = p;
    } else if (w < NPG * Gn + Gn * Mn) {      // ---- E rows: fp16 + e2 ----
        int r = w - NPG * Gn;
        float4 v = ((const float4*)(emb + (size_t)r * Dn))[lane];
        float s = v.x * v.x + v.y * v.y + v.z * v.z + v.w * v.w;
        #pragma unroll
        for (int o = 16; o; o >>= 1) s += __shfl_xor_sync(0xffffffffu, s, o);
        if (lane == 0) { g_e2[r] = s; g_e2b[r] = s + SCORE_BIAS; }
        uint2 p;
        p.x = pack_h2(v.x, v.y);
        p.y = pack_h2(v.z, v.w);
        ((uint2*)(g_Es + (size_t)r * Dn))[lane] = p;
    }
}

// ---------------------------------------------------------------------------
// vq: fp16 HMMA GEMM, A fragments register-resident, packed int-key top-2.
// 16 warps (4x4), warp tile 32q x 32c; BM=128 double-buffered, 1 sync/tile.
// ---------------------------------------------------------------------------
__global__ __launch_bounds__(512, 1)
void vq_kernel(const float* __restrict__ x, const float* __restrict__ emb) {
    extern __shared__ char sm[];
    const uint32_t sb   = smem_u32(sm);
    const int tid  = threadIdx.x;
    const int lane = tid & 31;
    const int wid  = tid >> 5;
    const int wrow = wid >> 2;              // 0..3  (32-query band)
    const int wcol = wid & 3;               // 0..3  (32-code band)
    const int g    = blockIdx.y;
    const int n0   = blockIdx.x * NTILE;

    const uint4* Bsrc = (const uint4*)(g_Es + (size_t)g * Mn * Dn);
    auto load_B = [&](int t) {
        const uint32_t boff = (t & 1) ? B_OFF1 : B_OFF0;
        const int m0 = t * BM;
        #pragma unroll
        for (int it = 0; it < 4; it++) {
            int ch = tid + it * 512;           // 2048 x 16B, gmem-coalesced
            int r = ch >> 4, j = ch & 15;
            int c = j >> 1, h = j & 1;
            uint32_t dst = sb + boff + c * 4096 + r * 32 + ((h * 16) ^ ((r & 4) ? 16 : 0));
            cp16(dst, Bsrc + (size_t)(m0 + r) * 16 + j);
        }
        if (tid < BM) cp4(sb + E2_OFF + (t & 1) * 512 + tid * 4, g_e2b + g * Mn + m0 + tid);
    };

    load_B(0); CP_COMMIT();                  // overlap with A staging

    // ---- A stage to smem (once): 2048 x 16B chunks ----
    {
        const uint4* Asrc = (const uint4*)(g_Xs + ((size_t)g * NPG + n0) * Dn);
        #pragma unroll
        for (int it = 0; it < 4; it++) {
            int ch = tid + it * 512;
            int r = ch & 127, j = ch >> 7;     // j 0..15
            uint4 v = Asrc[(size_t)r * 16 + j];
            int c = j >> 1, h = j & 1;
            uint32_t off = c * 4096 + r * 32 + ((h * 16) ^ ((r & 4) ? 16 : 0));
            *(uint4*)(sm + A_OFF + off) = v;
        }
    }
    __syncthreads();

    // ---- preload ALL A fragments into registers (constant across tiles) ----
    const int lr  = (lane & 7) + ((lane >> 3) & 1) * 8;   // row-in-16
    const int lkh = lane >> 4;                            // k half (0/1)
    uint32_t af[2][KCH][4];
    #pragma unroll
    for (int i = 0; i < 2; i++) {
        int ar = wrow * 32 + i * 16 + lr;
        uint32_t ab = sb + A_OFF + ar * 32 + ((lkh * 16) ^ ((ar & 4) ? 16 : 0));
        #pragma unroll
        for (int ks = 0; ks < KCH; ks++) ldsm_x4(af[i][ks], ab + ks * 4096);
    }

    uint32_t b_off[2];
    #pragma unroll
    for (int f = 0; f < 2; f++) {
        int bc = wcol * 32 + f * 16 + lr;
        b_off[f] = bc * 32 + ((lkh * 16) ^ ((bc & 4) ? 16 : 0));
    }

    // packed top-2 keys per row-slot: (score_bits & ~0xFFF) | code_idx
    uint32_t k1[4], k2[4];
    #pragma unroll
    for (int s = 0; s < 4; s++) { k1[s] = 0xFFFFFFFFu; k2[s] = 0xFFFFFFFFu; }

    for (int t = 0; t < NT; t++) {
        CP_WAIT0();
        __syncthreads();                 // tile t resident; prev buffer free
        if (t + 1 < NT) { load_B(t + 1); CP_COMMIT(); }

        const uint32_t bb = sb + ((t & 1) ? B_OFF1 : B_OFF0);
        float acc[2][4][4];
        #pragma unroll
        for (int i = 0; i < 2; i++)
            #pragma unroll
            for (int j = 0; j < 4; j++)
                #pragma unroll
                for (int e = 0; e < 4; e++) acc[i][j][e] = 0.0f;

        #pragma unroll
        for (int ks = 0; ks < KCH; ks++) {
            uint32_t bh[2][4];
            #pragma unroll
            for (int f = 0; f < 2; f++) ldsm_x4(bh[f], bb + b_off[f] + ks * 4096);
            #pragma unroll
            for (int i = 0; i < 2; i++)
                #pragma unroll
                for (int f = 0; f < 2; f++) {
                    mma16816(acc[i][f * 2 + 0], af[i][ks], bh[f][0], bh[f][2]);
                    mma16816(acc[i][f * 2 + 1], af[i][ks], bh[f][1], bh[f][3]);
                }
        }

        // ---- epilogue: key = pack(e2b + (-2 dot), idx); top-2 int-min ----
        const float* e2s = (const float*)(sm + E2_OFF + (t & 1) * 512);
        const int mbase = t * BM;
        #pragma unroll
        for (int jf = 0; jf < 4; jf++) {
            int c0 = wcol * 32 + (jf >> 1) * 16 + (jf & 1) * 8 + (lane & 3) * 2;
            float ea = e2s[c0], eb = e2s[c0 + 1];
            uint32_t ia = (uint32_t)(mbase + c0), ib = ia + 1;
            #pragma unroll
            for (int i = 0; i < 2; i++)
                #pragma unroll
                for (int rh = 0; rh < 2; rh++) {
                    int s = i * 2 + rh;
                    uint32_t ka = (__float_as_uint(acc[i][jf][rh * 2 + 0] + ea) & ~0xFFFu) | ia;
                    uint32_t kb = (__float_as_uint(acc[i][jf][rh * 2 + 1] + eb) & ~0xFFFu) | ib;
                    if (ka < k2[s]) { if (ka < k1[s]) { k2[s] = k1[s]; k1[s] = ka; } else k2[s] = ka; }
                    if (kb < k2[s]) { if (kb < k1[s]) { k2[s] = k1[s]; k1[s] = kb; } else k2[s] = kb; }
                }
        }
    }

    // ---- cross-lane/warp reduction: 16x top-2 keys -> row top-4 ----
    uint2* red = (uint2*)(sm + B_OFF0);      // [128 rows][16 slots] = 16 KB
    #pragma unroll
    for (int s = 0; s < 4; s++) {
        int row  = wrow * 32 + (s >> 1) * 16 + (s & 1) * 8 + (lane >> 2);
        int slot = wcol * 4 + (lane & 3);
        red[row * 16 + slot] = make_uint2(k1[s], k2[s]);
    }
    __syncthreads();

    if (tid < NTILE) {
        uint32_t tk[4] = {0xFFFFFFFFu, 0xFFFFFFFFu, 0xFFFFFFFFu, 0xFFFFFFFFu};
        auto ins = [&](uint32_t k) {
            if (k < tk[3]) {
                tk[3] = k;
                #pragma unroll
                for (int q = 3; q > 0; q--)
                    if (tk[q] < tk[q-1]) { uint32_t f = tk[q]; tk[q] = tk[q-1]; tk[q-1] = f; }
            }
        };
        #pragma unroll 4
        for (int q = 0; q < 16; q++) {
            uint2 c = red[tid * 16 + q];
            ins(c.x); ins(c.y);
        }
        const int n = n0 + tid;
        int best = (int)(tk[0] & 0xFFFu);
        float tv0 = __uint_as_float(tk[0] & ~0xFFFu);
        float tv1 = __uint_as_float(tk[1] & ~0xFFFu);
        if (tv1 - tv0 < RESCUE_TAU) {        // exact fp32 rescore of top-4
            const float* xr = x + ((size_t)n * Gn + g) * Dn;
            float bs = FLT_MAX; int bi = 0x7FFFFFFF;
            #pragma unroll
            for (int c = 0; c < 4; c++) {
                int cand = (int)(tk[c] & 0xFFFu);
                const float* er = emb + ((size_t)(g * Mn + cand)) * Dn;
                float d = 0.f;
                #pragma unroll 8
                for (int k = 0; k < Dn; k += 4) {
                    float4 xv = *(const float4*)(xr + k);
                    float4 ev = *(const float4*)(er + k);
                    d = fmaf(xv.x, ev.x, fmaf(xv.y, ev.y, fmaf(xv.z, ev.z, fmaf(xv.w, ev.w, d))));
                }
                float sc = fmaf(-2.f, d, g_e2[g * Mn + cand]);
                if (sc < bs || (sc == bs && cand < bi)) { bs = sc; bi = cand; }
            }
            best = bi;
        }
        g_idx[(size_t)n * Gn + g] = best;
    }
}

// ---------------------------------------------------------------------------
// gather + histogram + index write (one warp per (n,g) row)
// ---------------------------------------------------------------------------
__global__ void gather_kernel(const float* __restrict__ emb,
                              float* __restrict__ out) {
    int w    = (blockIdx.x * blockDim.x + threadIdx.x) >> 5;
    int lane = threadIdx.x & 31;
    if (w >= NPG * Gn) return;
    int g  = w & 3;
    int bi = g_idx[w];
    const float4* src = (const float4*)(emb + ((size_t)(g * Mn + bi)) * Dn);
    ((float4*)(out + (size_t)w * Dn))[lane] = src[lane];
    if (lane == 0) {
        out[IND_BASE + w] = (float)bi;
        atomicAdd(&out[CNT_BASE + g * Mn + bi], 1.0f);
    }
}

// ---------------------------------------------------------------------------
extern "C" void kernel_launch(void* const* d_in, const int* in_sizes, int n_in,
                              void* d_out, int out_size) {
    const float* x     = (const float*)d_in[0];
    const float* emb   = (const float*)d_in[1];
    const float* count = (const float*)d_in[2];
    float*       out   = (float*)d_out;

    cudaFuncSetAttribute(vq_kernel,
                         cudaFuncAttributeMaxDynamicSharedMemorySize, SMEM_TOTAL);

    prep_kernel<<<(NPG * Gn + Gn * Mn) * 32 / 256, 256>>>(x, emb, count, out);

    dim3 grid(NPG / NTILE, Gn);
    vq_kernel<<<grid, 512, SMEM_TOTAL>>>(x, emb);

    gather_kernel<<<(NPG * Gn * 32) / 256, 256>>>(emb, out);
}

// round 10
// speedup vs baseline: 5.9354x; 1.1361x over previous
#include <cuda_runtime.h>
#include <cuda_fp16.h>
#include <cstdint>
#include <float.h>

// ---------------- problem constants ----------------
#define Gn    4
#define Mn    4096
#define Dn    128
#define NPG   16384
#define NTILE 128              // queries per CTA
#define BM    128              // codes per streamed B tile
#define MH    2048             // codes per M-half
#define NT_H  (MH / BM)        // 16 tiles per half
#define KCH   8                // 8 k16 chunks (K=128)

#define XQ_SIZE  (NPG * Gn * Dn)
#define IND_BASE (XQ_SIZE)
#define CNT_BASE (XQ_SIZE + NPG * Gn)

#define SCORE_BIAS 512.0f      // makes scores positive
#define RESCUE_TAU 1.0f        // fp16 noise + 12-bit key masking (granularity ~0.25)

// ---------------- device scratch (allocation-free) ----------------
__device__ float  g_e2[Gn * Mn];       // exact, for rescue
__device__ float  g_e2b[Gn * Mn];      // e2 + SCORE_BIAS, for epilogue
__device__ __half g_Xs[(size_t)NPG * Gn * Dn];   // fp16(-2x)
__device__ __half g_Es[(size_t)Gn * Mn * Dn];    // fp16(e)
__device__ uint4  g_top[(size_t)NPG * Gn * 2];   // per (row, m-half): top-4 packed keys

// ---------------- smem layout (dynamic) ----------------
#define A_OFF   0               // 32 KB
#define B_OFF0  32768           // 32 KB
#define B_OFF1  65536           // 32 KB
#define E2_OFF  98304           // 2 x 128 floats
#define SMEM_TOTAL 99328

// ---------------- PTX helpers ----------------
__device__ __forceinline__ uint32_t smem_u32(const void* p) {
    uint32_t a;
    asm("{ .reg .u64 t; cvta.to.shared.u64 t, %1; cvt.u32.u64 %0, t; }" : "=r"(a) : "l"(p));
    return a;
}
__device__ __forceinline__ void ldsm_x4(uint32_t* r, uint32_t a) {
    asm volatile("ldmatrix.sync.aligned.m8n8.x4.shared.b16 {%0,%1,%2,%3}, [%4];"
                 : "=r"(r[0]), "=r"(r[1]), "=r"(r[2]), "=r"(r[3]) : "r"(a));
}
__device__ __forceinline__ void mma16816(float* d, const uint32_t* a, uint32_t b0, uint32_t b1) {
    asm volatile("mma.sync.aligned.m16n8k16.row.col.f32.f16.f16.f32 "
                 "{%0,%1,%2,%3}, {%4,%5,%6,%7}, {%8,%9}, {%0,%1,%2,%3};"
                 : "+f"(d[0]), "+f"(d[1]), "+f"(d[2]), "+f"(d[3])
                 : "r"(a[0]), "r"(a[1]), "r"(a[2]), "r"(a[3]), "r"(b0), "r"(b1));
}
__device__ __forceinline__ void cp16(uint32_t dst, const void* src) {
    asm volatile("cp.async.cg.shared.global [%0], [%1], 16;" :: "r"(dst), "l"(src));
}
__device__ __forceinline__ void cp4(uint32_t dst, const void* src) {
    asm volatile("cp.async.ca.shared.global [%0], [%1], 4;" :: "r"(dst), "l"(src));
}
#define CP_COMMIT() asm volatile("cp.async.commit_group;" ::: "memory")
#define CP_WAIT0()  asm volatile("cp.async.wait_group 0;" ::: "memory")

// ---------------------------------------------------------------------------
// prep: X -> fp16(-2x), E -> fp16(e), e2 (raw + biased), count copy.
// ---------------------------------------------------------------------------
__device__ __forceinline__ uint32_t pack_h2(float a, float b) {
    __half2 h = __floats2half2_rn(a, b);
    return *(uint32_t*)&h;
}

__global__ void prep_kernel(const float* __restrict__ x,
                            const float* __restrict__ emb,
                            const float* __restrict__ count,
                            float* __restrict__ out) {
    int gt   = blockIdx.x * blockDim.x + threadIdx.x;
    int w    = gt >> 5;
    int lane = gt & 31;
    if (gt < Gn * Mn) out[CNT_BASE + gt] = count[gt];

    if (w < NPG * Gn) {                       // ---- X rows: fp16(-2x) ----
        int g = w >> 14, n = w & (NPG - 1);
        float4 v = ((const float4*)(x + ((size_t)n * Gn + g) * Dn))[lane];
        uint2 p;
        p.x = pack_h2(-2.f * v.x, -2.f * v.y);
        p.y = pack_h2(-2.f * v.z, -2.f * v.w);
        ((uint2*)(g_Xs + (size_t)w * Dn))[lane] = p;
    } else if (w < NPG * Gn + Gn * Mn) {      // ---- E rows: fp16 + e2 ----
        int r = w - NPG * Gn;
        float4 v = ((const float4*)(emb + (size_t)r * Dn))[lane];
        float s = v.x * v.x + v.y * v.y + v.z * v.z + v.w * v.w;
        #pragma unroll
        for (int o = 16; o; o >>= 1) s += __shfl_xor_sync(0xffffffffu, s, o);
        if (lane == 0) { g_e2[r] = s; g_e2b[r] = s + SCORE_BIAS; }
        uint2 p;
        p.x = pack_h2(v.x, v.y);
        p.y = pack_h2(v.z, v.w);
        ((uint2*)(g_Es + (size_t)r * Dn))[lane] = p;
    }
}

// ---------------------------------------------------------------------------
// vq: fp16 HMMA GEMM over one M-half (2048 codes); emits row top-4 keys.
// grid = (128 n-tiles, 4 groups, 2 m-halves) = 1024 CTAs.
// ---------------------------------------------------------------------------
__global__ __launch_bounds__(512, 1)
void vq_kernel() {
    extern __shared__ char sm[];
    const uint32_t sb   = smem_u32(sm);
    const int tid  = threadIdx.x;
    const int lane = tid & 31;
    const int wid  = tid >> 5;
    const int wrow = wid >> 2;              // 0..3  (32-query band)
    const int wcol = wid & 3;               // 0..3  (32-code band)
    const int g    = blockIdx.y;
    const int n0   = blockIdx.x * NTILE;
    const int mh   = blockIdx.z;            // 0/1 m-half
    const int mh0  = mh * MH;

    const uint4* Bsrc = (const uint4*)(g_Es + ((size_t)g * Mn + mh0) * Dn);
    auto load_B = [&](int t) {
        const uint32_t boff = (t & 1) ? B_OFF1 : B_OFF0;
        const int m0 = t * BM;
        #pragma unroll
        for (int it = 0; it < 4; it++) {
            int ch = tid + it * 512;           // 2048 x 16B, gmem-coalesced
            int r = ch >> 4, j = ch & 15;
            int c = j >> 1, h = j & 1;
            uint32_t dst = sb + boff + c * 4096 + r * 32 + ((h * 16) ^ ((r & 4) ? 16 : 0));
            cp16(dst, Bsrc + (size_t)(m0 + r) * 16 + j);
        }
        if (tid < BM) cp4(sb + E2_OFF + (t & 1) * 512 + tid * 4, g_e2b + g * Mn + mh0 + m0 + tid);
    };

    load_B(0); CP_COMMIT();                  // overlap with A staging

    // ---- A stage to smem (once): 2048 x 16B chunks ----
    {
        const uint4* Asrc = (const uint4*)(g_Xs + ((size_t)g * NPG + n0) * Dn);
        #pragma unroll
        for (int it = 0; it < 4; it++) {
            int ch = tid + it * 512;
            int r = ch & 127, j = ch >> 7;     // j 0..15
            uint4 v = Asrc[(size_t)r * 16 + j];
            int c = j >> 1, h = j & 1;
            uint32_t off = c * 4096 + r * 32 + ((h * 16) ^ ((r & 4) ? 16 : 0));
            *(uint4*)(sm + A_OFF + off) = v;
        }
    }
    __syncthreads();

    // ---- preload ALL A fragments into registers (constant across tiles) ----
    const int lr  = (lane & 7) + ((lane >> 3) & 1) * 8;   // row-in-16
    const int lkh = lane >> 4;                            // k half (0/1)
    uint32_t af[2][KCH][4];
    #pragma unroll
    for (int i = 0; i < 2; i++) {
        int ar = wrow * 32 + i * 16 + lr;
        uint32_t ab = sb + A_OFF + ar * 32 + ((lkh * 16) ^ ((ar & 4) ? 16 : 0));
        #pragma unroll
        for (int ks = 0; ks < KCH; ks++) ldsm_x4(af[i][ks], ab + ks * 4096);
    }

    uint32_t b_off[2];
    #pragma unroll
    for (int f = 0; f < 2; f++) {
        int bc = wcol * 32 + f * 16 + lr;
        b_off[f] = bc * 32 + ((lkh * 16) ^ ((bc & 4) ? 16 : 0));
    }

    // packed top-2 keys per row-slot: (score_bits & ~0xFFF) | code_idx(global)
    uint32_t k1[4], k2[4];
    #pragma unroll
    for (int s = 0; s < 4; s++) { k1[s] = 0xFFFFFFFFu; k2[s] = 0xFFFFFFFFu; }

    for (int t = 0; t < NT_H; t++) {
        CP_WAIT0();
        __syncthreads();                 // tile t resident; prev buffer free
        if (t + 1 < NT_H) { load_B(t + 1); CP_COMMIT(); }

        const uint32_t bb = sb + ((t & 1) ? B_OFF1 : B_OFF0);
        float acc[2][4][4];
        #pragma unroll
        for (int i = 0; i < 2; i++)
            #pragma unroll
            for (int j = 0; j < 4; j++)
                #pragma unroll
                for (int e = 0; e < 4; e++) acc[i][j][e] = 0.0f;

        #pragma unroll
        for (int ks = 0; ks < KCH; ks++) {
            uint32_t bh[2][4];
            #pragma unroll
            for (int f = 0; f < 2; f++) ldsm_x4(bh[f], bb + b_off[f] + ks * 4096);
            #pragma unroll
            for (int i = 0; i < 2; i++)
                #pragma unroll
                for (int f = 0; f < 2; f++) {
                    mma16816(acc[i][f * 2 + 0], af[i][ks], bh[f][0], bh[f][2]);
                    mma16816(acc[i][f * 2 + 1], af[i][ks], bh[f][1], bh[f][3]);
                }
        }

        // ---- epilogue: key = pack(e2b + (-2 dot), global idx); top-2 ----
        const float* e2s = (const float*)(sm + E2_OFF + (t & 1) * 512);
        const int mbase = mh0 + t * BM;
        #pragma unroll
        for (int jf = 0; jf < 4; jf++) {
            int c0 = wcol * 32 + (jf >> 1) * 16 + (jf & 1) * 8 + (lane & 3) * 2;
            float ea = e2s[c0], eb = e2s[c0 + 1];
            uint32_t ia = (uint32_t)(mbase + c0), ib = ia + 1;
            #pragma unroll
            for (int i = 0; i < 2; i++)
                #pragma unroll
                for (int rh = 0; rh < 2; rh++) {
                    int s = i * 2 + rh;
                    uint32_t ka = (__float_as_uint(acc[i][jf][rh * 2 + 0] + ea) & ~0xFFFu) | ia;
                    uint32_t kb = (__float_as_uint(acc[i][jf][rh * 2 + 1] + eb) & ~0xFFFu) | ib;
                    if (ka < k2[s]) { if (ka < k1[s]) { k2[s] = k1[s]; k1[s] = ka; } else k2[s] = ka; }
                    if (kb < k2[s]) { if (kb < k1[s]) { k2[s] = k1[s]; k1[s] = kb; } else k2[s] = kb; }
                }
        }
    }

    // ---- cross-lane/warp reduction: 32 keys -> row top-4 -> g_top ----
    uint2* red = (uint2*)(sm + B_OFF0);      // [128 rows][16 slots] = 16 KB
    #pragma unroll
    for (int s = 0; s < 4; s++) {
        int row  = wrow * 32 + (s >> 1) * 16 + (s & 1) * 8 + (lane >> 2);
        int slot = wcol * 4 + (lane & 3);
        red[row * 16 + slot] = make_uint2(k1[s], k2[s]);
    }
    __syncthreads();

    if (tid < NTILE) {
        uint32_t tk[4] = {0xFFFFFFFFu, 0xFFFFFFFFu, 0xFFFFFFFFu, 0xFFFFFFFFu};
        auto ins = [&](uint32_t k) {
            if (k < tk[3]) {
                tk[3] = k;
                #pragma unroll
                for (int q = 3; q > 0; q--)
                    if (tk[q] < tk[q-1]) { uint32_t f = tk[q]; tk[q] = tk[q-1]; tk[q-1] = f; }
            }
        };
        #pragma unroll 4
        for (int q = 0; q < 16; q++) {
            uint2 c = red[tid * 16 + q];
            ins(c.x); ins(c.y);
        }
        g_top[((size_t)(g * NPG + n0 + tid)) * 2 + mh] =
            make_uint4(tk[0], tk[1], tk[2], tk[3]);
    }
}

// ---------------------------------------------------------------------------
// merge halves + rescue + gather + histogram (one warp per (n,g) row)
// ---------------------------------------------------------------------------
__global__ void merge_gather_kernel(const float* __restrict__ x,
                                    const float* __restrict__ emb,
                                    float* __restrict__ out) {
    int w    = (blockIdx.x * blockDim.x + threadIdx.x) >> 5;
    int lane = threadIdx.x & 31;
    if (w >= NPG * Gn) return;
    int g = w & 3, n = w >> 2;

    const uint4 h0 = g_top[((size_t)(g * NPG + n)) * 2 + 0];
    const uint4 h1 = g_top[((size_t)(g * NPG + n)) * 2 + 1];
    uint32_t tk[4] = {0xFFFFFFFFu, 0xFFFFFFFFu, 0xFFFFFFFFu, 0xFFFFFFFFu};
    auto ins = [&](uint32_t k) {
        if (k < tk[3]) {
            tk[3] = k;
            #pragma unroll
            for (int q = 3; q > 0; q--)
                if (tk[q] < tk[q-1]) { uint32_t f = tk[q]; tk[q] = tk[q-1]; tk[q-1] = f; }
        }
    };
    ins(h0.x); ins(h0.y); ins(h0.z); ins(h0.w);
    ins(h1.x); ins(h1.y); ins(h1.z); ins(h1.w);

    int best = (int)(tk[0] & 0xFFFu);
    float tv0 = __uint_as_float(tk[0] & ~0xFFFu);
    float tv1 = __uint_as_float(tk[1] & ~0xFFFu);

    if (tv1 - tv0 < RESCUE_TAU) {            // warp-cooperative exact rescore
        float4 xv = ((const float4*)(x + ((size_t)n * Gn + g) * Dn))[lane];
        float bs = FLT_MAX; int bi = 0x7FFFFFFF;
        #pragma unroll
        for (int c = 0; c < 4; c++) {
            int cand = (int)(tk[c] & 0xFFFu);
            float4 ev = ((const float4*)(emb + ((size_t)(g * Mn + cand)) * Dn))[lane];
            float d = fmaf(xv.x, ev.x, fmaf(xv.y, ev.y, fmaf(xv.z, ev.z, xv.w * ev.w)));
            #pragma unroll
            for (int o = 16; o; o >>= 1) d += __shfl_xor_sync(0xffffffffu, d, o);
            float sc = fmaf(-2.f, d, g_e2[g * Mn + cand]);
            if (sc < bs || (sc == bs && cand < bi)) { bs = sc; bi = cand; }
        }
        best = bi;
    }

    // gather x_quant row + index + histogram
    const float4* src = (const float4*)(emb + ((size_t)(g * Mn + best)) * Dn);
    ((float4*)(out + (size_t)w * Dn))[lane] = src[lane];
    if (lane == 0) {
        out[IND_BASE + w] = (float)best;
        atomicAdd(&out[CNT_BASE + g * Mn + best], 1.0f);
    }
}

// ---------------------------------------------------------------------------
extern "C" void kernel_launch(void* const* d_in, const int* in_sizes, int n_in,
                              void* d_out, int out_size) {
    const float* x     = (const float*)d_in[0];
    const float* emb   = (const float*)d_in[1];
    const float* count = (const float*)d_in[2];
    float*       out   = (float*)d_out;

    cudaFuncSetAttribute(vq_kernel,
                         cudaFuncAttributeMaxDynamicSharedMemorySize, SMEM_TOTAL);

    prep_kernel<<<(NPG * Gn + Gn * Mn) * 32 / 256, 256>>>(x, emb, count, out);

    dim3 grid(NPG / NTILE, Gn, 2);
    vq_kernel<<<grid, 512, SMEM_TOTAL>>>();

    merge_gather_kernel<<<(NPG * Gn * 32) / 256, 256>>>(x, emb, out);
}